// round 14
// baseline (speedup 1.0000x reference)
#include <cuda_runtime.h>
#include <cuda_bf16.h>
#include <cuda_fp16.h>
#include <cstdint>

#define NB      131072
#define D       256
#define LEAVES  4
#define MID     2

typedef unsigned long long u64;
union U64F2 { u64 u; float2 f; };

__device__ __forceinline__ uint32_t smem_u32(const void* p) {
    uint32_t a;
    asm("{ .reg .u64 t; cvta.to.shared.u64 t, %1; cvt.u32.u64 %0, t; }"
        : "=r"(a) : "l"(p));
    return a;
}

__device__ __forceinline__ uint32_t pack_bf2(__nv_bfloat16 a, __nv_bfloat16 b) {
    __nv_bfloat162 p = __halves2bfloat162(a, b);
    return *reinterpret_cast<uint32_t*>(&p);
}
__device__ __forceinline__ uint32_t pack_h2(__half a, __half b) {
    __half2 p = __halves2half2(a, b);
    return *reinterpret_cast<uint32_t*>(&p);
}

__device__ __forceinline__
void mma_bf16(float* c, const uint32_t a[4], uint32_t b0, uint32_t b1)
{
    asm("mma.sync.aligned.m16n8k16.row.col.f32.bf16.bf16.f32 "
        "{%0,%1,%2,%3}, {%4,%5,%6,%7}, {%8,%9}, {%0,%1,%2,%3};"
        : "+f"(c[0]), "+f"(c[1]), "+f"(c[2]), "+f"(c[3])
        : "r"(a[0]), "r"(a[1]), "r"(a[2]), "r"(a[3]), "r"(b0), "r"(b1));
}
__device__ __forceinline__
void mma_f16(float* c, const uint32_t a[4], uint32_t b0, uint32_t b1)
{
    asm("mma.sync.aligned.m16n8k16.row.col.f32.f16.f16.f32 "
        "{%0,%1,%2,%3}, {%4,%5,%6,%7}, {%8,%9}, {%0,%1,%2,%3};"
        : "+f"(c[0]), "+f"(c[1]), "+f"(c[2]), "+f"(c[3])
        : "r"(a[0]), "r"(a[1]), "r"(a[2]), "r"(a[3]), "r"(b0), "r"(b1));
}

#define LDSM_X4(r0, r1, r2, r3, addr)                                        \
    asm volatile("ldmatrix.sync.aligned.m8n8.x4.shared.b16 {%0,%1,%2,%3}, [%4];" \
        : "=r"(r0), "=r"(r1), "=r"(r2), "=r"(r3) : "r"(addr))

// ======================= global scratch =======================
__device__ int g_idx[NB];
__device__ int g_perm[NB];
__device__ int g_hist[LEAVES];
__device__ int g_base[LEAVES];
// CHUNK-MAJOR weight images: [mat(7)][kc32(8)][plane(2)][n(256)][32 u16]
//   plane0 = fp16(W), plane1 = bf16(W - fp16(W));  B col-major per chunk.
__device__ __align__(16) unsigned short g_wimg[7 * 131072];

// ======================= gate / sort =======================
constexpr int GTILE = 64;
constexpr int GSTR  = D + 8;
constexpr int GOFF_SX  = 0;
constexpr int GOFF_WG  = GOFF_SX + GTILE * GSTR;
constexpr int GOFF_LOG = GOFF_WG + D * LEAVES;
constexpr int GOFF_H   = GOFF_LOG + GTILE * LEAVES;
constexpr int GATE_BYTES = (GOFF_H + LEAVES) * (int)sizeof(float);

__global__ void init_kernel() {
    if (threadIdx.x < LEAVES) g_hist[threadIdx.x] = 0;
}

__global__ void __launch_bounds__(256, 2)
gate_kernel(const float* __restrict__ x, const float* __restrict__ Wg,
            const float* __restrict__ bg)
{
    extern __shared__ float sm[];
    float* sX = sm + GOFF_SX;  float* sWg = sm + GOFF_WG;
    float* sLog = sm + GOFF_LOG;
    int* sH = reinterpret_cast<int*>(sm + GOFF_H);
    const int tid = threadIdx.x;
    const size_t row0 = (size_t)blockIdx.x * GTILE;

    const float4* xg = reinterpret_cast<const float4*>(x + row0 * D);
#pragma unroll
    for (int i = 0; i < (GTILE * D / 4) / 256; i++) {
        int li = tid + i * 256;
        int r = li / (D / 4), c4 = li % (D / 4);
        float4 v = xg[r * (D / 4) + c4];
        float* dst = &sX[r * GSTR + c4 * 4];
        dst[0] = v.x; dst[1] = v.y; dst[2] = v.z; dst[3] = v.w;
    }
    for (int i = tid; i < D * LEAVES; i += 256) sWg[i] = Wg[i];
    if (tid < LEAVES) sH[tid] = 0;
    __syncthreads();
    {
        int r = tid & (GTILE - 1);
        int e = tid >> 6;
        float acc = bg[e];
        const float* xr = &sX[r * GSTR];
#pragma unroll 8
        for (int d = 0; d < D; d++) acc = fmaf(xr[d], sWg[d * LEAVES + e], acc);
        sLog[r * LEAVES + e] = acc;
    }
    __syncthreads();
    if (tid < GTILE) {
        float best = sLog[tid * LEAVES];
        int bi = 0;
#pragma unroll
        for (int e = 1; e < LEAVES; e++) {
            float v = sLog[tid * LEAVES + e];
            if (v > best) { best = v; bi = e; }
        }
        g_idx[row0 + tid] = bi;
        atomicAdd(&sH[bi], 1);
    }
    __syncthreads();
    if (tid < LEAVES) atomicAdd(&g_hist[tid], sH[tid]);
}

__global__ void scan_kernel() {
    int b = 0;
    for (int e = 0; e < LEAVES; e++) { g_base[e] = b; b += g_hist[e]; }
}

__global__ void scatter_kernel() {
    __shared__ int cnt[LEAVES];
    __shared__ int boff[LEAVES];
    const int tid = threadIdx.x;
    const int r = blockIdx.x * blockDim.x + tid;
    if (tid < LEAVES) cnt[tid] = 0;
    __syncthreads();
    int e = g_idx[r];
    int my = atomicAdd(&cnt[e], 1);
    __syncthreads();
    if (tid < LEAVES) boff[tid] = atomicAdd(&g_base[tid], cnt[tid]);
    __syncthreads();
    g_perm[boff[e] + my] = r;
}

// === weight prep: fp32 W[k][n] -> chunk-major fp16 / bf16-residual images ===
// dst u16 index: mat*131072 + kc32*16384 + plane*8192 + n*32 + (k&31)
__global__ void prep_w_kernel(const float* __restrict__ Wl,
                              const float* __restrict__ Wm,
                              const float* __restrict__ Wr)
{
    int gid = blockIdx.x * 256 + threadIdx.x;      // 7*65536 total
    int mat = gid >> 16;
    int rem = gid & 0xFFFF;
    int n = rem >> 8, k = rem & 255;
    float v;
    if (mat < 4)      v = Wl[mat * 65536 + k * 256 + n];
    else if (mat < 6) v = Wm[(mat - 4) * 65536 + k * 256 + n];
    else              v = Wr[k * 256 + n];
    __half h = __float2half_rn(v);
    float lof = v - __half2float(h);
    __nv_bfloat16 l = __float2bfloat16(lof);
    size_t base = (size_t)mat * 131072 + (k >> 5) * 16384 + n * 32 + (k & 31);
    g_wimg[base]        = __half_as_ushort(h);
    g_wimg[base + 8192] = __bfloat16_as_ushort(l);
}

// === main mma.sync kernel: 64-row blocks, 2 CTAs/SM, k16 single-buffer ====
constexpr int ROWS_BLK  = 64;
constexpr int A_STR_B   = 264 * 2;                 // 528 (conflict-free ldmatrix)
constexpr int OFF_AHI   = 0;                       // fp16(value) plane
constexpr int OFF_ABF   = ROWS_BLK * A_STR_B;      // 33792, bf16(value) plane
constexpr int OFF_B     = 2 * ROWS_BLK * A_STR_B;  // 67584
constexpr int B_STR     = 48;                      // 12 words: conflict-free
constexpr int B_PLANE_B = 256 * B_STR;             // 12288 (k16 chunk plane)
constexpr int B_CHUNK_B = 2 * B_PLANE_B;           // 24576, single buffer
constexpr int OFF_BIAS  = OFF_B + B_CHUNK_B;       // 92160
constexpr int OFF_ORIG  = OFF_BIAS + 768 * 4;      // 95232
constexpr int MMA_SMEM  = OFF_ORIG + 256;          // 95488 -> 2 CTAs/SM

__global__ void __launch_bounds__(256, 2)
tree_mma_kernel(const float* __restrict__ x,
                const float* __restrict__ b_leaf,
                const float* __restrict__ b_mid,
                const float* __restrict__ b_root,
                float* __restrict__ out)
{
    extern __shared__ char smc[];
    int* sOrig = reinterpret_cast<int*>(smc + OFF_ORIG);
    float* sBias = reinterpret_cast<float*>(smc + OFF_BIAS);
    const uint32_t sbU = smem_u32(smc);

    const int tid = threadIdx.x;
    const int lane = tid & 31, w = tid >> 5;       // 8 warps
    const int wm = w & 1, wn = w >> 1;             // 2 x 4 warp grid, tile 32x64
    const int g = lane >> 2, tg = lane & 3;
    const size_t row0 = (size_t)blockIdx.x * ROWS_BLK;

    if (tid < ROWS_BLK) sOrig[tid] = g_perm[row0 + tid];
    __syncthreads();
    const int eL = g_idx[sOrig[0]];
    if (eL != g_idx[sOrig[ROWS_BLK - 1]]) return;  // mixed 64-tile -> fallback
    const int eM = eL >> 1;
    const int matIdx[3] = { eL, 4 + eM, 6 };

    for (int i = tid; i < 256; i += 256) {
        sBias[i]       = b_leaf[eL * 256 + i];
        sBias[256 + i] = b_mid[eM * 256 + i];
        sBias[512 + i] = b_root[i];
    }

    // ---- A init: thread -> (row tid>>2, 64-col segment tid&3) ----
    {
        int r = tid >> 2, seg = tid & 3;
        const float4* xr = reinterpret_cast<const float4*>(
                               x + (size_t)sOrig[r] * D) + seg * 16;
        char* aH = smc + OFF_AHI + r * A_STR_B + seg * 128;
        char* aB = smc + OFF_ABF + r * A_STR_B + seg * 128;
#pragma unroll
        for (int i = 0; i < 16; i++) {
            float4 f = xr[i];
            uint2 hv, lv;
            hv.x = pack_h2(__float2half_rn(f.x), __float2half_rn(f.y));
            hv.y = pack_h2(__float2half_rn(f.z), __float2half_rn(f.w));
            lv.x = pack_bf2(__float2bfloat16(f.x), __float2bfloat16(f.y));
            lv.y = pack_bf2(__float2bfloat16(f.z), __float2bfloat16(f.w));
            *reinterpret_cast<uint2*>(aH + i * 8) = hv;
            *reinterpret_cast<uint2*>(aB + i * 8) = lv;
        }
    }

    // B staging: thread -> (plane sp, two n-rows 2*sq, 2*sq+1); k16 chunk
    // src per row: 32B at  mat*131072 + kc32*16384 + sp*8192 + n*32 + half*16
    const int sp = tid >> 7, sq = tid & 127;
    auto ldB = [&](int l, int c16, uint4* pf) {       // LDG into regs
        const unsigned short* s0 = g_wimg + (size_t)matIdx[l] * 131072
            + (c16 >> 1) * 16384 + sp * 8192 + (2 * sq) * 32 + (c16 & 1) * 16;
        pf[0] = reinterpret_cast<const uint4*>(s0)[0];
        pf[1] = reinterpret_cast<const uint4*>(s0)[1];
        pf[2] = reinterpret_cast<const uint4*>(s0 + 32)[0];
        pf[3] = reinterpret_cast<const uint4*>(s0 + 32)[1];
    };
    auto stB = [&](const uint4* pf) {                 // STS from regs
        char* d0 = smc + OFF_B + sp * B_PLANE_B + (2 * sq) * B_STR;
        reinterpret_cast<uint4*>(d0)[0] = pf[0];
        reinterpret_cast<uint4*>(d0)[1] = pf[1];
        reinterpret_cast<uint4*>(d0 + B_STR)[0] = pf[2];
        reinterpret_cast<uint4*>(d0 + B_STR)[1] = pf[3];
    };

    // prologue: stage chunk (0,0)
    {
        uint4 pf[4];
        ldB(0, 0, pf);
        stB(pf);
    }

    // ldmatrix base addresses
    uint32_t aBase[2];
#pragma unroll
    for (int mt = 0; mt < 2; mt++)
        aBase[mt] = sbU + OFF_AHI
                  + (wm * 32 + mt * 16 + (lane & 15)) * A_STR_B
                  + (lane >> 4) * 16;
    const uint32_t bBase = sbU + OFF_B
        + (wn * 64 + (lane & 7) + ((lane >> 4) << 3)) * B_STR
        + (((lane >> 3) & 1) << 4);

    float acc[2][8][4];
#pragma unroll
    for (int mt = 0; mt < 2; mt++)
#pragma unroll
        for (int nt = 0; nt < 8; nt++)
#pragma unroll
            for (int q = 0; q < 4; q++) acc[mt][nt][q] = 0.f;

    __syncthreads();   // A planes + biases + B chunk 0 visible

#pragma unroll 1
    for (int l = 0; l < 3; l++) {
#pragma unroll 1
        for (int c = 0; c < 16; c++) {       // k16 chunks
            // prefetch next chunk into regs (LDG latency hidden by compute)
            bool hasNext = (c < 15) || (l < 2);
            uint4 pf[4];
            if (hasNext) {
                int nl = (c < 15) ? l : l + 1;
                int nc = (c < 15) ? c + 1 : 0;
                ldB(nl, nc, pf);
            }

            // ---- compute k16 chunk ----
            const uint32_t koffA = c * 32;
            uint32_t aH[2][4], aB[2][4];
#pragma unroll
            for (int mt = 0; mt < 2; mt++) {
                LDSM_X4(aH[mt][0], aH[mt][1], aH[mt][2], aH[mt][3],
                        aBase[mt] + koffA);
                LDSM_X4(aB[mt][0], aB[mt][1], aB[mt][2], aB[mt][3],
                        aBase[mt] + (OFF_ABF - OFF_AHI) + koffA);
            }
#pragma unroll
            for (int op = 0; op < 4; op++) {
                uint32_t bh0, bh1, bh2, bh3, bl0, bl1, bl2, bl3;
                LDSM_X4(bh0, bh1, bh2, bh3, bBase + op * (16 * B_STR));
                LDSM_X4(bl0, bl1, bl2, bl3, bBase + op * (16 * B_STR) + B_PLANE_B);
#pragma unroll
                for (int mt = 0; mt < 2; mt++) {
                    mma_f16 (acc[mt][2 * op],     aH[mt], bh0, bh1);
                    mma_bf16(acc[mt][2 * op],     aB[mt], bl0, bl1);
                    mma_f16 (acc[mt][2 * op + 1], aH[mt], bh2, bh3);
                    mma_bf16(acc[mt][2 * op + 1], aB[mt], bl2, bl3);
                }
            }

            __syncthreads();   // all warps done reading buffer
            if (hasNext) {
                stB(pf);       // overwrite single buffer
                __syncthreads();
            }
        }

        // ---- layer epilogue ----
        const float* sB = sBias + l * 256;
        if (l < 2) {
#pragma unroll
            for (int mt = 0; mt < 2; mt++) {
#pragma unroll
                for (int nt = 0; nt < 8; nt++) {
                    int col = wn * 64 + nt * 8 + tg * 2;
                    float b0 = sB[col], b1 = sB[col + 1];
                    int rlo = wm * 32 + mt * 16 + g;
#pragma unroll
                    for (int half = 0; half < 2; half++) {
                        int r = rlo + half * 8;
                        float v0 = fmaxf(acc[mt][nt][2 * half]     + b0, 0.f);
                        float v1 = fmaxf(acc[mt][nt][2 * half + 1] + b1, 0.f);
                        uint32_t hv = pack_h2(__float2half_rn(v0),
                                              __float2half_rn(v1));
                        uint32_t lv = pack_bf2(__float2bfloat16(v0),
                                               __float2bfloat16(v1));
                        char* pa = smc + OFF_AHI + r * A_STR_B + col * 2;
                        *reinterpret_cast<uint32_t*>(pa) = hv;
                        *reinterpret_cast<uint32_t*>(pa + (OFF_ABF - OFF_AHI)) = lv;
                        acc[mt][nt][2 * half] = 0.f;
                        acc[mt][nt][2 * half + 1] = 0.f;
                    }
                }
            }
            __syncthreads();   // A rewrite visible before next layer
        } else {
#pragma unroll
            for (int mt = 0; mt < 2; mt++) {
#pragma unroll
                for (int half = 0; half < 2; half++) {
                    int r = wm * 32 + mt * 16 + g + half * 8;
                    float* orow = out + (size_t)sOrig[r] * D;
#pragma unroll
                    for (int nt = 0; nt < 8; nt++) {
                        int col = wn * 64 + nt * 8 + tg * 2;
                        float2 v;
                        v.x = fmaxf(acc[mt][nt][2 * half]     + sB[col],     0.f);
                        v.y = fmaxf(acc[mt][nt][2 * half + 1] + sB[col + 1], 0.f);
                        *reinterpret_cast<float2*>(orow + col) = v;
                    }
                }
            }
        }
    }
}

// ======================= FFMA2 fallback for mixed 64-tiles =======================
constexpr int FTILE = 64;
constexpr int FKC = 16;
constexpr int FSTR = D + 8;
constexpr int FOFF_SX = 0;
constexpr int FOFF_SW = FOFF_SX + FTILE * FSTR;
constexpr int FOFF_BLEAF = FOFF_SW + FKC * D;
constexpr int FOFF_BMID = FOFF_BLEAF + LEAVES * D;
constexpr int FOFF_BROOT = FOFF_BMID + MID * D;
constexpr int FOFF_ORIG = FOFF_BROOT + D;
constexpr int FOFF_E = FOFF_ORIG + FTILE;
constexpr int FOFF_MM = FOFF_E + FTILE;
constexpr int FB_BYTES = (FOFF_MM + 2) * (int)sizeof(float);

#define FMA_F32X2(d, a, b, c) \
    asm("fma.rn.f32x2 %0, %1, %2, %3;" : "=l"(d) : "l"(a), "l"(b), "l"(c))
#define PACK2(d, xx) \
    asm("mov.b64 %0, {%1, %1};" : "=l"(d) : "r"(xx))

template <bool MASKED>
__device__ __forceinline__
void fb_gemm(const float* __restrict__ Wglob, float* sW, const float* sX,
             const float m[8], u64 (&acc2)[8][4], int tid, int r0, int c0)
{
#pragma unroll 1
    for (int kc = 0; kc < D; kc += FKC) {
        __syncthreads();
        const float4* wg4 = reinterpret_cast<const float4*>(Wglob + (size_t)kc * D);
        float4* sW4 = reinterpret_cast<float4*>(sW);
#pragma unroll
        for (int i = 0; i < (FKC * D / 4) / 256; i++)
            sW4[tid + i * 256] = wg4[tid + i * 256];
        __syncthreads();
#pragma unroll
        for (int k4 = 0; k4 < FKC; k4 += 4) {
            float4 a4[8];
#pragma unroll
            for (int i = 0; i < 8; i++) {
                a4[i] = *reinterpret_cast<const float4*>(&sX[(r0 + i) * FSTR + kc + k4]);
                if (MASKED) {
                    a4[i].x *= m[i]; a4[i].y *= m[i];
                    a4[i].z *= m[i]; a4[i].w *= m[i];
                }
            }
#pragma unroll
            for (int kk = 0; kk < 4; kk++) {
                const ulonglong2* bp =
                    reinterpret_cast<const ulonglong2*>(&sW[(k4 + kk) * D + c0]);
                ulonglong2 b01 = bp[0];
                ulonglong2 b23 = bp[1];
#pragma unroll
                for (int i = 0; i < 8; i++) {
                    float av = (kk == 0) ? a4[i].x : (kk == 1) ? a4[i].y
                             : (kk == 2) ? a4[i].z : a4[i].w;
                    u64 a2;
                    PACK2(a2, __float_as_uint(av));
                    FMA_F32X2(acc2[i][0], a2, b01.x, acc2[i][0]);
                    FMA_F32X2(acc2[i][1], a2, b01.y, acc2[i][1]);
                    FMA_F32X2(acc2[i][2], a2, b23.x, acc2[i][2]);
                    FMA_F32X2(acc2[i][3], a2, b23.y, acc2[i][3]);
                }
            }
        }
    }
}

__global__ void __launch_bounds__(256, 2)
fallback_kernel(const float* __restrict__ x,
                const float* __restrict__ W_leaf, const float* __restrict__ b_leaf,
                const float* __restrict__ W_mid,  const float* __restrict__ b_mid,
                const float* __restrict__ W_root, const float* __restrict__ b_root,
                float* __restrict__ out)
{
    // process exactly the mixed 64-tiles the main kernel skipped
    const size_t t0 = (size_t)blockIdx.x * FTILE;
    if (g_idx[g_perm[t0]] == g_idx[g_perm[t0 + FTILE - 1]]) return;

    extern __shared__ float sm[];
    float* sX = sm + FOFF_SX;  float* sW = sm + FOFF_SW;
    float* sBlf = sm + FOFF_BLEAF;  float* sBmd = sm + FOFF_BMID;
    float* sBrt = sm + FOFF_BROOT;
    int* sOrig = reinterpret_cast<int*>(sm + FOFF_ORIG);
    int* sE = reinterpret_cast<int*>(sm + FOFF_E);
    int* sMM = reinterpret_cast<int*>(sm + FOFF_MM);

    const int tid = threadIdx.x;
    const size_t row0 = (size_t)blockIdx.x * FTILE;
    const int tx = tid & 31, ty = tid >> 5;
    const int r0 = ty * 8, c0 = tx * 8;

    if (tid < FTILE) {
        int orig = g_perm[row0 + tid];
        sOrig[tid] = orig;
        sE[tid] = g_idx[orig];
    }
    if (tid == FTILE) { sMM[0] = LEAVES; sMM[1] = -1; }
    __syncthreads();

#pragma unroll
    for (int i = 0; i < (FTILE * D / 4) / 256; i++) {
        int li = tid + i * 256;
        int r = li / (D / 4), c4 = li % (D / 4);
        const float4* src = reinterpret_cast<const float4*>(x + (size_t)sOrig[r] * D);
        float4 v = src[c4];
        float* dst = &sX[r * FSTR + c4 * 4];
        dst[0] = v.x; dst[1] = v.y; dst[2] = v.z; dst[3] = v.w;
    }
    for (int i = tid; i < LEAVES * D; i += 256) sBlf[i] = b_leaf[i];
    for (int i = tid; i < MID * D;    i += 256) sBmd[i] = b_mid[i];
    for (int i = tid; i < D;          i += 256) sBrt[i] = b_root[i];
    if (tid < FTILE) {
        atomicMin(&sMM[0], sE[tid]);
        atomicMax(&sMM[1], sE[tid]);
    }
    __syncthreads();

    const int emin = sMM[0], emax = sMM[1];
    u64 acc2[8][4];
#pragma unroll
    for (int i = 0; i < 8; i++)
#pragma unroll
        for (int j = 0; j < 4; j++) acc2[i][j] = 0ull;
    float m[8];

    if (emin == emax) {
        fb_gemm<false>(W_leaf + (size_t)emin * D * D, sW, sX, m, acc2, tid, r0, c0);
    } else {
        for (int e = emin; e <= emax; e++) {
#pragma unroll
            for (int i = 0; i < 8; i++) m[i] = (sE[r0 + i] == e) ? 1.f : 0.f;
            fb_gemm<true>(W_leaf + (size_t)e * D * D, sW, sX, m, acc2, tid, r0, c0);
        }
    }
#pragma unroll
    for (int i = 0; i < 8; i++) {
        int e = sE[r0 + i];
#pragma unroll
        for (int p = 0; p < 4; p++) {
            U64F2 u; u.u = acc2[i][p];
            sX[(r0 + i) * FSTR + c0 + 2 * p]     = fmaxf(u.f.x + sBlf[e * D + c0 + 2 * p], 0.f);
            sX[(r0 + i) * FSTR + c0 + 2 * p + 1] = fmaxf(u.f.y + sBlf[e * D + c0 + 2 * p + 1], 0.f);
            acc2[i][p] = 0ull;
        }
    }

    const int pmin = emin >> 1, pmax = emax >> 1;
    if (pmin == pmax) {
        fb_gemm<false>(W_mid + (size_t)pmin * D * D, sW, sX, m, acc2, tid, r0, c0);
    } else {
        for (int p = pmin; p <= pmax; p++) {
#pragma unroll
            for (int i = 0; i < 8; i++) m[i] = ((sE[r0 + i] >> 1) == p) ? 1.f : 0.f;
            fb_gemm<true>(W_mid + (size_t)p * D * D, sW, sX, m, acc2, tid, r0, c0);
        }
    }
#pragma unroll
    for (int i = 0; i < 8; i++) {
        int pp = sE[r0 + i] >> 1;
#pragma unroll
        for (int p = 0; p < 4; p++) {
            U64F2 u; u.u = acc2[i][p];
            sX[(r0 + i) * FSTR + c0 + 2 * p]     = fmaxf(u.f.x + sBmd[pp * D + c0 + 2 * p], 0.f);
            sX[(r0 + i) * FSTR + c0 + 2 * p + 1] = fmaxf(u.f.y + sBmd[pp * D + c0 + 2 * p + 1], 0.f);
            acc2[i][p] = 0ull;
        }
    }

    fb_gemm<false>(W_root, sW, sX, m, acc2, tid, r0, c0);
#pragma unroll
    for (int i = 0; i < 8; i++) {
        float v[8];
#pragma unroll
        for (int p = 0; p < 4; p++) {
            U64F2 u; u.u = acc2[i][p];
            v[2 * p]     = fmaxf(u.f.x + sBrt[c0 + 2 * p],     0.f);
            v[2 * p + 1] = fmaxf(u.f.y + sBrt[c0 + 2 * p + 1], 0.f);
        }
        float4* o = reinterpret_cast<float4*>(out + (size_t)sOrig[r0 + i] * D + c0);
        o[0] = make_float4(v[0], v[1], v[2], v[3]);
        o[1] = make_float4(v[4], v[5], v[6], v[7]);
    }
}

// ======================= launch =======================
extern "C" void kernel_launch(void* const* d_in, const int* in_sizes, int n_in,
                              void* d_out, int out_size)
{
    const float* x      = (const float*)d_in[0];
    const float* Wg     = (const float*)d_in[1];
    const float* bg     = (const float*)d_in[2];
    const float* W_leaf = (const float*)d_in[3];
    const float* b_leaf = (const float*)d_in[4];
    const float* W_mid  = (const float*)d_in[5];
    const float* b_mid  = (const float*)d_in[6];
    const float* W_root = (const float*)d_in[7];
    const float* b_root = (const float*)d_in[8];
    float* out = (float*)d_out;

    cudaFuncSetAttribute(gate_kernel,
                         cudaFuncAttributeMaxDynamicSharedMemorySize, GATE_BYTES);
    cudaFuncSetAttribute(tree_mma_kernel,
                         cudaFuncAttributeMaxDynamicSharedMemorySize, MMA_SMEM);
    cudaFuncSetAttribute(fallback_kernel,
                         cudaFuncAttributeMaxDynamicSharedMemorySize, FB_BYTES);

    init_kernel<<<1, 32>>>();
    prep_w_kernel<<<7 * 65536 / 256, 256>>>(W_leaf, W_mid, W_root);
    gate_kernel<<<NB / GTILE, 256, GATE_BYTES>>>(x, Wg, bg);
    scan_kernel<<<1, 1>>>();
    scatter_kernel<<<NB / 256, 256>>>();
    tree_mma_kernel<<<NB / ROWS_BLK, 256, MMA_SMEM>>>(x, b_leaf, b_mid, b_root, out);
    fallback_kernel<<<NB / FTILE, 256, FB_BYTES>>>(
        x, W_leaf, b_leaf, W_mid, b_mid, W_root, b_root, out);
}

// round 15
// speedup vs baseline: 1.4733x; 1.4733x over previous
#include <cuda_runtime.h>
#include <cuda_bf16.h>
#include <cuda_fp16.h>
#include <cstdint>

#define NB      131072
#define D       256
#define LEAVES  4
#define MID     2

typedef unsigned long long u64;
union U64F2 { u64 u; float2 f; };

__device__ __forceinline__ uint32_t smem_u32(const void* p) {
    uint32_t a;
    asm("{ .reg .u64 t; cvta.to.shared.u64 t, %1; cvt.u32.u64 %0, t; }"
        : "=r"(a) : "l"(p));
    return a;
}

__device__ __forceinline__ uint32_t pack_bf2(__nv_bfloat16 a, __nv_bfloat16 b) {
    __nv_bfloat162 p = __halves2bfloat162(a, b);
    return *reinterpret_cast<uint32_t*>(&p);
}
__device__ __forceinline__ uint32_t pack_h2(__half a, __half b) {
    __half2 p = __halves2half2(a, b);
    return *reinterpret_cast<uint32_t*>(&p);
}

__device__ __forceinline__
void mma_bf16(float* c, const uint32_t a[4], uint32_t b0, uint32_t b1)
{
    asm("mma.sync.aligned.m16n8k16.row.col.f32.bf16.bf16.f32 "
        "{%0,%1,%2,%3}, {%4,%5,%6,%7}, {%8,%9}, {%0,%1,%2,%3};"
        : "+f"(c[0]), "+f"(c[1]), "+f"(c[2]), "+f"(c[3])
        : "r"(a[0]), "r"(a[1]), "r"(a[2]), "r"(a[3]), "r"(b0), "r"(b1));
}
__device__ __forceinline__
void mma_f16(float* c, const uint32_t a[4], uint32_t b0, uint32_t b1)
{
    asm("mma.sync.aligned.m16n8k16.row.col.f32.f16.f16.f32 "
        "{%0,%1,%2,%3}, {%4,%5,%6,%7}, {%8,%9}, {%0,%1,%2,%3};"
        : "+f"(c[0]), "+f"(c[1]), "+f"(c[2]), "+f"(c[3])
        : "r"(a[0]), "r"(a[1]), "r"(a[2]), "r"(a[3]), "r"(b0), "r"(b1));
}

#define LDSM_X4(r0, r1, r2, r3, addr)                                        \
    asm volatile("ldmatrix.sync.aligned.m8n8.x4.shared.b16 {%0,%1,%2,%3}, [%4];" \
        : "=r"(r0), "=r"(r1), "=r"(r2), "=r"(r3) : "r"(addr))

// ======================= global scratch =======================
__device__ int g_idx[NB];
__device__ int g_perm[NB];
__device__ int g_hist[LEAVES];
__device__ int g_cursor[LEAVES];
// CHUNK-MAJOR weight images: [mat(7)][kc32(8)][plane(2)][n(256)][32 u16]
//   plane0 = fp16(W), plane1 = bf16(W - fp16(W));  B col-major per chunk.
__device__ __align__(16) unsigned short g_wimg[7 * 131072];

// === weight prep (also zeroes hist/cursor): fp32 W[k][n] -> chunk-major images ===
__global__ void prep_w_kernel(const float* __restrict__ Wl,
                              const float* __restrict__ Wm,
                              const float* __restrict__ Wr)
{
    if (blockIdx.x == 0 && threadIdx.x < LEAVES) {
        g_hist[threadIdx.x] = 0;
        g_cursor[threadIdx.x] = 0;
    }
    int gid = blockIdx.x * 256 + threadIdx.x;      // 7*65536 total
    int mat = gid >> 16;
    int rem = gid & 0xFFFF;
    int n = rem >> 8, k = rem & 255;
    float v;
    if (mat < 4)      v = Wl[mat * 65536 + k * 256 + n];
    else if (mat < 6) v = Wm[(mat - 4) * 65536 + k * 256 + n];
    else              v = Wr[k * 256 + n];
    __half h = __float2half_rn(v);
    float lof = v - __half2float(h);
    __nv_bfloat16 l = __float2bfloat16(lof);
    size_t base = (size_t)mat * 131072 + (k >> 5) * 16384 + n * 32 + (k & 31);
    g_wimg[base]        = __half_as_ushort(h);
    g_wimg[base + 8192] = __bfloat16_as_ushort(l);
}

// ======================= gate =======================
constexpr int GTILE = 64;
constexpr int GSTR  = D + 8;
constexpr int GOFF_SX  = 0;
constexpr int GOFF_WG  = GOFF_SX + GTILE * GSTR;
constexpr int GOFF_LOG = GOFF_WG + D * LEAVES;
constexpr int GOFF_H   = GOFF_LOG + GTILE * LEAVES;
constexpr int GATE_BYTES = (GOFF_H + LEAVES) * (int)sizeof(float);

__global__ void __launch_bounds__(256, 2)
gate_kernel(const float* __restrict__ x, const float* __restrict__ Wg,
            const float* __restrict__ bg)
{
    extern __shared__ float sm[];
    float* sX = sm + GOFF_SX;  float* sWg = sm + GOFF_WG;
    float* sLog = sm + GOFF_LOG;
    int* sH = reinterpret_cast<int*>(sm + GOFF_H);
    const int tid = threadIdx.x;
    const size_t row0 = (size_t)blockIdx.x * GTILE;

    const float4* xg = reinterpret_cast<const float4*>(x + row0 * D);
#pragma unroll
    for (int i = 0; i < (GTILE * D / 4) / 256; i++) {
        int li = tid + i * 256;
        int r = li / (D / 4), c4 = li % (D / 4);
        float4 v = xg[r * (D / 4) + c4];
        float* dst = &sX[r * GSTR + c4 * 4];
        dst[0] = v.x; dst[1] = v.y; dst[2] = v.z; dst[3] = v.w;
    }
    for (int i = tid; i < D * LEAVES; i += 256) sWg[i] = Wg[i];
    if (tid < LEAVES) sH[tid] = 0;
    __syncthreads();
    {
        int r = tid & (GTILE - 1);
        int e = tid >> 6;
        float acc = bg[e];
        const float* xr = &sX[r * GSTR];
#pragma unroll 8
        for (int d = 0; d < D; d++) acc = fmaf(xr[d], sWg[d * LEAVES + e], acc);
        sLog[r * LEAVES + e] = acc;
    }
    __syncthreads();
    if (tid < GTILE) {     // first-max wins (matches jnp.argmax)
        float best = sLog[tid * LEAVES];
        int bi = 0;
#pragma unroll
        for (int e = 1; e < LEAVES; e++) {
            float v = sLog[tid * LEAVES + e];
            if (v > best) { best = v; bi = e; }
        }
        g_idx[row0 + tid] = bi;
        atomicAdd(&sH[bi], 1);
    }
    __syncthreads();
    if (tid < LEAVES) atomicAdd(&g_hist[tid], sH[tid]);
}

// counting-sort scatter: bases from local prefix of completed g_hist + cursor
__global__ void scatter_kernel() {
    __shared__ int cnt[LEAVES];
    __shared__ int boff[LEAVES];
    const int tid = threadIdx.x;
    const int r = blockIdx.x * blockDim.x + tid;
    if (tid < LEAVES) cnt[tid] = 0;
    __syncthreads();
    int e = g_idx[r];
    int my = atomicAdd(&cnt[e], 1);
    __syncthreads();
    if (tid < LEAVES) {
        int base = 0;
#pragma unroll
        for (int j = 0; j < LEAVES; j++)
            if (j < tid) base += g_hist[j];
        boff[tid] = base + atomicAdd(&g_cursor[tid], cnt[tid]);
    }
    __syncthreads();
    g_perm[boff[e] + my] = r;
}

// ======= main mma.sync kernel (R12, byte-identical) =======
constexpr int A_STR_B   = 264 * 2;                 // 528
constexpr int OFF_AHI   = 0;                       // fp16(value) plane
constexpr int OFF_ABF   = 67584;                   // bf16(value) plane
constexpr int OFF_B     = 135168;
constexpr int B_PLANE_B = 256 * 40 * 2;            // 20480 (80B rows, k32)
constexpr int B_BUF_B   = 2 * B_PLANE_B;           // 40960
constexpr int OFF_BIAS  = OFF_B + 2 * B_BUF_B;     // 217088
constexpr int OFF_ORIG  = OFF_BIAS + 768 * 4;      // 220160
constexpr int MMA_SMEM  = OFF_ORIG + 512;          // 220672

__global__ void __launch_bounds__(512, 1)
tree_mma_kernel(const float* __restrict__ x,
                const float* __restrict__ b_leaf,
                const float* __restrict__ b_mid,
                const float* __restrict__ b_root,
                float* __restrict__ out)
{
    extern __shared__ char smc[];
    int* sOrig = reinterpret_cast<int*>(smc + OFF_ORIG);
    float* sBias = reinterpret_cast<float*>(smc + OFF_BIAS);
    const uint32_t sbU = smem_u32(smc);

    const int tid = threadIdx.x;
    const int lane = tid & 31, w = tid >> 5;       // 16 warps
    const int wm = w & 3, wn = w >> 2;             // 4 x 4 warp grid
    const int g = lane >> 2, tg = lane & 3;
    const size_t row0 = (size_t)blockIdx.x * 128;

    if (tid < 128) sOrig[tid] = g_perm[row0 + tid];
    __syncthreads();
    const int eL = g_idx[sOrig[0]];
    if (eL != g_idx[sOrig[127]]) return;          // mixed tile -> fallback
    const int eM = eL >> 1;
    const int matIdx[3] = { eL, 4 + eM, 6 };

    for (int i = tid; i < 256; i += 512) {
        sBias[i]       = b_leaf[eL * 256 + i];
        sBias[256 + i] = b_mid[eM * 256 + i];
        sBias[512 + i] = b_root[i];
    }

    // ---- A init: thread -> (row tid>>2, 64-col segment tid&3) ----
    // plane0 = fp16(x), plane1 = bf16(x)
    {
        int r = tid >> 2, seg = tid & 3;
        const float4* xr = reinterpret_cast<const float4*>(
                               x + (size_t)sOrig[r] * D) + seg * 16;
        char* aH = smc + OFF_AHI + r * A_STR_B + seg * 128;
        char* aB = smc + OFF_ABF + r * A_STR_B + seg * 128;
#pragma unroll
        for (int i = 0; i < 16; i++) {
            float4 f = xr[i];
            uint2 hv, lv;
            hv.x = pack_h2(__float2half_rn(f.x), __float2half_rn(f.y));
            hv.y = pack_h2(__float2half_rn(f.z), __float2half_rn(f.w));
            lv.x = pack_bf2(__float2bfloat16(f.x), __float2bfloat16(f.y));
            lv.y = pack_bf2(__float2bfloat16(f.z), __float2bfloat16(f.w));
            *reinterpret_cast<uint2*>(aH + i * 8) = hv;
            *reinterpret_cast<uint2*>(aB + i * 8) = lv;
        }
    }

    // B staging coords: thread -> (plane sp, n-row sn); src 64B CONTIGUOUS
    const int sp = tid >> 8, sn = tid & 255;
    const uint32_t stgDstOff = sp * B_PLANE_B + sn * 80;

    // ---- stage B chunk 0 of layer 0 into buffer 0 (coalesced) ----
    {
        const uint4* src = reinterpret_cast<const uint4*>(
            g_wimg + (size_t)matIdx[0] * 131072 + sp * 8192 + sn * 32);
        uint4* dst = reinterpret_cast<uint4*>(smc + OFF_B + stgDstOff);
        dst[0] = src[0]; dst[1] = src[1]; dst[2] = src[2]; dst[3] = src[3];
    }
    __syncthreads();

    // ldmatrix base addresses (byte offsets in shared space)
    uint32_t aBase[2];
#pragma unroll
    for (int mt = 0; mt < 2; mt++)
        aBase[mt] = sbU + OFF_AHI
                  + (wm * 32 + mt * 16 + (lane & 15)) * A_STR_B
                  + (lane >> 4) * 16;
    const uint32_t bBase = sbU + OFF_B
        + (wn * 64 + (lane & 7) + ((lane >> 4) << 3)) * 80
        + (((lane >> 3) & 1) << 4);

    float acc[2][8][4];
#pragma unroll
    for (int mt = 0; mt < 2; mt++)
#pragma unroll
        for (int nt = 0; nt < 8; nt++)
#pragma unroll
            for (int q = 0; q < 4; q++) acc[mt][nt][q] = 0.f;

    int cur = 0;

#pragma unroll 1
    for (int l = 0; l < 3; l++) {
#pragma unroll 1
        for (int kc = 0; kc < 8; kc++) {
            // prefetch next chunk (next layer's chunk 0 at boundaries) — 64B contiguous
            bool hasNext = (kc < 7) || (l < 2);
            uint4 pf0, pf1, pf2, pf3;
            if (hasNext) {
                int nl  = (kc < 7) ? l : l + 1;
                int nkc = (kc < 7) ? kc + 1 : 0;
                const uint4* src = reinterpret_cast<const uint4*>(
                    g_wimg + (size_t)matIdx[nl] * 131072 + nkc * 16384
                    + sp * 8192 + sn * 32);
                pf0 = src[0]; pf1 = src[1]; pf2 = src[2]; pf3 = src[3];
            }

            // ---- compute 2 k16-steps on buffer `cur` ----
#pragma unroll
            for (int kk = 0; kk < 2; kk++) {
                const uint32_t koffA = kc * 64 + kk * 32;
                uint32_t aH[2][4], aB[2][4];
#pragma unroll
                for (int mt = 0; mt < 2; mt++) {
                    LDSM_X4(aH[mt][0], aH[mt][1], aH[mt][2], aH[mt][3],
                            aBase[mt] + koffA);
                    LDSM_X4(aB[mt][0], aB[mt][1], aB[mt][2], aB[mt][3],
                            aBase[mt] + (OFF_ABF - OFF_AHI) + koffA);
                }
                const uint32_t bk = bBase + cur * B_BUF_B + kk * 32;
#pragma unroll
                for (int op = 0; op < 4; op++) {
                    uint32_t bh0, bh1, bh2, bh3, bl0, bl1, bl2, bl3;
                    LDSM_X4(bh0, bh1, bh2, bh3, bk + op * (16 * 80));
                    LDSM_X4(bl0, bl1, bl2, bl3, bk + op * (16 * 80) + B_PLANE_B);
#pragma unroll
                    for (int mt = 0; mt < 2; mt++) {
                        mma_f16 (acc[mt][2 * op],     aH[mt], bh0, bh1);
                        mma_bf16(acc[mt][2 * op],     aB[mt], bl0, bl1);
                        mma_f16 (acc[mt][2 * op + 1], aH[mt], bh2, bh3);
                        mma_bf16(acc[mt][2 * op + 1], aB[mt], bl2, bl3);
                    }
                }
            }

            if (hasNext) {
                uint4* dst = reinterpret_cast<uint4*>(
                    smc + OFF_B + (cur ^ 1) * B_BUF_B + stgDstOff);
                dst[0] = pf0; dst[1] = pf1; dst[2] = pf2; dst[3] = pf3;
            }
            __syncthreads();
            cur ^= 1;
        }

        // ---- epilogue ----
        const float* sB = sBias + l * 256;
        if (l < 2) {
            // bias + relu + store fp16/bf16 planes for next layer
#pragma unroll
            for (int mt = 0; mt < 2; mt++) {
#pragma unroll
                for (int nt = 0; nt < 8; nt++) {
                    int col = wn * 64 + nt * 8 + tg * 2;
                    float b0 = sB[col], b1 = sB[col + 1];
                    int rlo = wm * 32 + mt * 16 + g;
#pragma unroll
                    for (int half = 0; half < 2; half++) {
                        int r = rlo + half * 8;
                        float v0 = fmaxf(acc[mt][nt][2 * half]     + b0, 0.f);
                        float v1 = fmaxf(acc[mt][nt][2 * half + 1] + b1, 0.f);
                        uint32_t hv = pack_h2(__float2half_rn(v0),
                                              __float2half_rn(v1));
                        uint32_t lv = pack_bf2(__float2bfloat16(v0),
                                               __float2bfloat16(v1));
                        char* pa = smc + OFF_AHI + r * A_STR_B + col * 2;
                        *reinterpret_cast<uint32_t*>(pa) = hv;
                        *reinterpret_cast<uint32_t*>(pa + (OFF_ABF - OFF_AHI)) = lv;
                        acc[mt][nt][2 * half] = 0.f;
                        acc[mt][nt][2 * half + 1] = 0.f;
                    }
                }
            }
            __syncthreads();   // A rewrite visible before next layer
        } else {
            // bias + relu + scatter to original rows
#pragma unroll
            for (int mt = 0; mt < 2; mt++) {
#pragma unroll
                for (int half = 0; half < 2; half++) {
                    int r = wm * 32 + mt * 16 + g + half * 8;
                    float* orow = out + (size_t)sOrig[r] * D;
#pragma unroll
                    for (int nt = 0; nt < 8; nt++) {
                        int col = wn * 64 + nt * 8 + tg * 2;
                        float2 v;
                        v.x = fmaxf(acc[mt][nt][2 * half]     + sB[col],     0.f);
                        v.y = fmaxf(acc[mt][nt][2 * half + 1] + sB[col + 1], 0.f);
                        *reinterpret_cast<float2*>(orow + col) = v;
                    }
                }
            }
        }
    }
}

// ======================= FFMA2 fallback for mixed 128-tiles =======================
constexpr int FTILE = 64;
constexpr int FKC = 16;
constexpr int FSTR = D + 8;
constexpr int FOFF_SX = 0;
constexpr int FOFF_SW = FOFF_SX + FTILE * FSTR;
constexpr int FOFF_BLEAF = FOFF_SW + FKC * D;
constexpr int FOFF_BMID = FOFF_BLEAF + LEAVES * D;
constexpr int FOFF_BROOT = FOFF_BMID + MID * D;
constexpr int FOFF_ORIG = FOFF_BROOT + D;
constexpr int FOFF_E = FOFF_ORIG + FTILE;
constexpr int FOFF_MM = FOFF_E + FTILE;
constexpr int FB_BYTES = (FOFF_MM + 2) * (int)sizeof(float);

#define FMA_F32X2(d, a, b, c) \
    asm("fma.rn.f32x2 %0, %1, %2, %3;" : "=l"(d) : "l"(a), "l"(b), "l"(c))
#define PACK2(d, xx) \
    asm("mov.b64 %0, {%1, %1};" : "=l"(d) : "r"(xx))

template <bool MASKED>
__device__ __forceinline__
void fb_gemm(const float* __restrict__ Wglob, float* sW, const float* sX,
             const float m[8], u64 (&acc2)[8][4], int tid, int r0, int c0)
{
#pragma unroll 1
    for (int kc = 0; kc < D; kc += FKC) {
        __syncthreads();
        const float4* wg4 = reinterpret_cast<const float4*>(Wglob + (size_t)kc * D);
        float4* sW4 = reinterpret_cast<float4*>(sW);
#pragma unroll
        for (int i = 0; i < (FKC * D / 4) / 256; i++)
            sW4[tid + i * 256] = wg4[tid + i * 256];
        __syncthreads();
#pragma unroll
        for (int k4 = 0; k4 < FKC; k4 += 4) {
            float4 a4[8];
#pragma unroll
            for (int i = 0; i < 8; i++) {
                a4[i] = *reinterpret_cast<const float4*>(&sX[(r0 + i) * FSTR + kc + k4]);
                if (MASKED) {
                    a4[i].x *= m[i]; a4[i].y *= m[i];
                    a4[i].z *= m[i]; a4[i].w *= m[i];
                }
            }
#pragma unroll
            for (int kk = 0; kk < 4; kk++) {
                const ulonglong2* bp =
                    reinterpret_cast<const ulonglong2*>(&sW[(k4 + kk) * D + c0]);
                ulonglong2 b01 = bp[0];
                ulonglong2 b23 = bp[1];
#pragma unroll
                for (int i = 0; i < 8; i++) {
                    float av = (kk == 0) ? a4[i].x : (kk == 1) ? a4[i].y
                             : (kk == 2) ? a4[i].z : a4[i].w;
                    u64 a2;
                    PACK2(a2, __float_as_uint(av));
                    FMA_F32X2(acc2[i][0], a2, b01.x, acc2[i][0]);
                    FMA_F32X2(acc2[i][1], a2, b01.y, acc2[i][1]);
                    FMA_F32X2(acc2[i][2], a2, b23.x, acc2[i][2]);
                    FMA_F32X2(acc2[i][3], a2, b23.y, acc2[i][3]);
                }
            }
        }
    }
}

__global__ void __launch_bounds__(256, 2)
fallback_kernel(const float* __restrict__ x,
                const float* __restrict__ W_leaf, const float* __restrict__ b_leaf,
                const float* __restrict__ W_mid,  const float* __restrict__ b_mid,
                const float* __restrict__ W_root, const float* __restrict__ b_root,
                float* __restrict__ out)
{
    const size_t t128 = (size_t)(blockIdx.x >> 1) * 128;
    if (g_idx[g_perm[t128]] == g_idx[g_perm[t128 + 127]]) return;

    extern __shared__ float sm[];
    float* sX = sm + FOFF_SX;  float* sW = sm + FOFF_SW;
    float* sBlf = sm + FOFF_BLEAF;  float* sBmd = sm + FOFF_BMID;
    float* sBrt = sm + FOFF_BROOT;
    int* sOrig = reinterpret_cast<int*>(sm + FOFF_ORIG);
    int* sE = reinterpret_cast<int*>(sm + FOFF_E);
    int* sMM = reinterpret_cast<int*>(sm + FOFF_MM);

    const int tid = threadIdx.x;
    const size_t row0 = (size_t)blockIdx.x * FTILE;
    const int tx = tid & 31, ty = tid >> 5;
    const int r0 = ty * 8, c0 = tx * 8;

    if (tid < FTILE) {
        int orig = g_perm[row0 + tid];
        sOrig[tid] = orig;
        sE[tid] = g_idx[orig];
    }
    if (tid == FTILE) { sMM[0] = LEAVES; sMM[1] = -1; }
    __syncthreads();

#pragma unroll
    for (int i = 0; i < (FTILE * D / 4) / 256; i++) {
        int li = tid + i * 256;
        int r = li / (D / 4), c4 = li % (D / 4);
        const float4* src = reinterpret_cast<const float4*>(x + (size_t)sOrig[r] * D);
        float4 v = src[c4];
        float* dst = &sX[r * FSTR + c4 * 4];
        dst[0] = v.x; dst[1] = v.y; dst[2] = v.z; dst[3] = v.w;
    }
    for (int i = tid; i < LEAVES * D; i += 256) sBlf[i] = b_leaf[i];
    for (int i = tid; i < MID * D;    i += 256) sBmd[i] = b_mid[i];
    for (int i = tid; i < D;          i += 256) sBrt[i] = b_root[i];
    if (tid < FTILE) {
        atomicMin(&sMM[0], sE[tid]);
        atomicMax(&sMM[1], sE[tid]);
    }
    __syncthreads();

    const int emin = sMM[0], emax = sMM[1];
    u64 acc2[8][4];
#pragma unroll
    for (int i = 0; i < 8; i++)
#pragma unroll
        for (int j = 0; j < 4; j++) acc2[i][j] = 0ull;
    float m[8];

    if (emin == emax) {
        fb_gemm<false>(W_leaf + (size_t)emin * D * D, sW, sX, m, acc2, tid, r0, c0);
    } else {
        for (int e = emin; e <= emax; e++) {
#pragma unroll
            for (int i = 0; i < 8; i++) m[i] = (sE[r0 + i] == e) ? 1.f : 0.f;
            fb_gemm<true>(W_leaf + (size_t)e * D * D, sW, sX, m, acc2, tid, r0, c0);
        }
    }
#pragma unroll
    for (int i = 0; i < 8; i++) {
        int e = sE[r0 + i];
#pragma unroll
        for (int p = 0; p < 4; p++) {
            U64F2 u; u.u = acc2[i][p];
            sX[(r0 + i) * FSTR + c0 + 2 * p]     = fmaxf(u.f.x + sBlf[e * D + c0 + 2 * p], 0.f);
            sX[(r0 + i) * FSTR + c0 + 2 * p + 1] = fmaxf(u.f.y + sBlf[e * D + c0 + 2 * p + 1], 0.f);
            acc2[i][p] = 0ull;
        }
    }

    const int pmin = emin >> 1, pmax = emax >> 1;
    if (pmin == pmax) {
        fb_gemm<false>(W_mid + (size_t)pmin * D * D, sW, sX, m, acc2, tid, r0, c0);
    } else {
        for (int p = pmin; p <= pmax; p++) {
#pragma unroll
            for (int i = 0; i < 8; i++) m[i] = ((sE[r0 + i] >> 1) == p) ? 1.f : 0.f;
            fb_gemm<true>(W_mid + (size_t)p * D * D, sW, sX, m, acc2, tid, r0, c0);
        }
    }
#pragma unroll
    for (int i = 0; i < 8; i++) {
        int pp = sE[r0 + i] >> 1;
#pragma unroll
        for (int p = 0; p < 4; p++) {
            U64F2 u; u.u = acc2[i][p];
            sX[(r0 + i) * FSTR + c0 + 2 * p]     = fmaxf(u.f.x + sBmd[pp * D + c0 + 2 * p], 0.f);
            sX[(r0 + i) * FSTR + c0 + 2 * p + 1] = fmaxf(u.f.y + sBmd[pp * D + c0 + 2 * p + 1], 0.f);
            acc2[i][p] = 0ull;
        }
    }

    fb_gemm<false>(W_root, sW, sX, m, acc2, tid, r0, c0);
#pragma unroll
    for (int i = 0; i < 8; i++) {
        float v[8];
#pragma unroll
        for (int p = 0; p < 4; p++) {
            U64F2 u; u.u = acc2[i][p];
            v[2 * p]     = fmaxf(u.f.x + sBrt[c0 + 2 * p],     0.f);
            v[2 * p + 1] = fmaxf(u.f.y + sBrt[c0 + 2 * p + 1], 0.f);
        }
        float4* o = reinterpret_cast<float4*>(out + (size_t)sOrig[r0 + i] * D + c0);
        o[0] = make_float4(v[0], v[1], v[2], v[3]);
        o[1] = make_float4(v[4], v[5], v[6], v[7]);
    }
}

// ======================= launch =======================
extern "C" void kernel_launch(void* const* d_in, const int* in_sizes, int n_in,
                              void* d_out, int out_size)
{
    const float* x      = (const float*)d_in[0];
    const float* Wg     = (const float*)d_in[1];
    const float* bg     = (const float*)d_in[2];
    const float* W_leaf = (const float*)d_in[3];
    const float* b_leaf = (const float*)d_in[4];
    const float* W_mid  = (const float*)d_in[5];
    const float* b_mid  = (const float*)d_in[6];
    const float* W_root = (const float*)d_in[7];
    const float* b_root = (const float*)d_in[8];
    float* out = (float*)d_out;

    cudaFuncSetAttribute(gate_kernel,
                         cudaFuncAttributeMaxDynamicSharedMemorySize, GATE_BYTES);
    cudaFuncSetAttribute(tree_mma_kernel,
                         cudaFuncAttributeMaxDynamicSharedMemorySize, MMA_SMEM);
    cudaFuncSetAttribute(fallback_kernel,
                         cudaFuncAttributeMaxDynamicSharedMemorySize, FB_BYTES);

    prep_w_kernel<<<7 * 65536 / 256, 256>>>(W_leaf, W_mid, W_root);
    gate_kernel<<<NB / GTILE, 256, GATE_BYTES>>>(x, Wg, bg);
    scatter_kernel<<<NB / 256, 256>>>();
    tree_mma_kernel<<<NB / 128, 512, MMA_SMEM>>>(x, b_leaf, b_mid, b_root, out);
    fallback_kernel<<<NB / FTILE, 256, FB_BYTES>>>(
        x, W_leaf, b_leaf, W_mid, b_mid, W_root, b_root, out);
}

// round 16
// speedup vs baseline: 1.4886x; 1.0104x over previous
#include <cuda_runtime.h>
#include <cuda_bf16.h>
#include <cuda_fp16.h>
#include <cstdint>

#define NB      131072
#define D       256
#define LEAVES  4
#define MID     2

typedef unsigned long long u64;
union U64F2 { u64 u; float2 f; };

__device__ __forceinline__ uint32_t smem_u32(const void* p) {
    uint32_t a;
    asm("{ .reg .u64 t; cvta.to.shared.u64 t, %1; cvt.u32.u64 %0, t; }"
        : "=r"(a) : "l"(p));
    return a;
}

__device__ __forceinline__ uint32_t pack_bf2(__nv_bfloat16 a, __nv_bfloat16 b) {
    __nv_bfloat162 p = __halves2bfloat162(a, b);
    return *reinterpret_cast<uint32_t*>(&p);
}
__device__ __forceinline__ uint32_t pack_h2(__half a, __half b) {
    __half2 p = __halves2half2(a, b);
    return *reinterpret_cast<uint32_t*>(&p);
}

__device__ __forceinline__
void mma_bf16(float* c, const uint32_t a[4], uint32_t b0, uint32_t b1)
{
    asm("mma.sync.aligned.m16n8k16.row.col.f32.bf16.bf16.f32 "
        "{%0,%1,%2,%3}, {%4,%5,%6,%7}, {%8,%9}, {%0,%1,%2,%3};"
        : "+f"(c[0]), "+f"(c[1]), "+f"(c[2]), "+f"(c[3])
        : "r"(a[0]), "r"(a[1]), "r"(a[2]), "r"(a[3]), "r"(b0), "r"(b1));
}
__device__ __forceinline__
void mma_f16(float* c, const uint32_t a[4], uint32_t b0, uint32_t b1)
{
    asm("mma.sync.aligned.m16n8k16.row.col.f32.f16.f16.f32 "
        "{%0,%1,%2,%3}, {%4,%5,%6,%7}, {%8,%9}, {%0,%1,%2,%3};"
        : "+f"(c[0]), "+f"(c[1]), "+f"(c[2]), "+f"(c[3])
        : "r"(a[0]), "r"(a[1]), "r"(a[2]), "r"(a[3]), "r"(b0), "r"(b1));
}

#define LDSM_X4(r0, r1, r2, r3, addr)                                        \
    asm volatile("ldmatrix.sync.aligned.m8n8.x4.shared.b16 {%0,%1,%2,%3}, [%4];" \
        : "=r"(r0), "=r"(r1), "=r"(r2), "=r"(r3) : "r"(addr))

// ======================= global scratch =======================
__device__ int g_idx[NB];
__device__ int g_perm[NB];
__device__ int g_hist[LEAVES];
__device__ int g_cursor[LEAVES];
// CHUNK-MAJOR weight images: [mat(7)][kc32(8)][plane(2)][n(256)][32 u16]
__device__ __align__(16) unsigned short g_wimg[7 * 131072];

// === weight prep: block = (mat, kc32); coalesced read, smem transpose,
//     coalesced 64B-per-row writes. Also zeroes hist/cursor (block 0). ===
__global__ void __launch_bounds__(256, 2)
prep_w_kernel(const float* __restrict__ Wl,
              const float* __restrict__ Wm,
              const float* __restrict__ Wr)
{
    __shared__ unsigned short sHi[256 * 32];
    __shared__ unsigned short sLo[256 * 32];

    const int tid = threadIdx.x;
    if (blockIdx.x == 0 && tid < LEAVES) {
        g_hist[tid] = 0;
        g_cursor[tid] = 0;
    }
    const int mat = blockIdx.x >> 3;       // 0..6
    const int kc  = blockIdx.x & 7;        // 0..7
    const float* W = (mat < 4) ? (Wl + (size_t)mat * 65536)
                   : (mat < 6) ? (Wm + (size_t)(mat - 4) * 65536)
                               : Wr;

    const int n = tid;                     // 0..255
#pragma unroll 1
    for (int kk = 0; kk < 32; kk++) {
        float v = W[(size_t)(kc * 32 + kk) * 256 + n];   // coalesced
        __half h = __float2half_rn(v);
        float lof = v - __half2float(h);
        sHi[n * 32 + kk] = __half_as_ushort(h);
        sLo[n * 32 + kk] = __bfloat16_as_ushort(__float2bfloat16(lof));
    }
    __syncthreads();

    // write [n][32] rows: 64B contiguous per thread, warp = 2KB coalesced
    unsigned short* dH = g_wimg + (size_t)mat * 131072 + kc * 16384 + n * 32;
    unsigned short* dL = dH + 8192;
    const uint4* sh = reinterpret_cast<const uint4*>(sHi + n * 32);
    const uint4* sl = reinterpret_cast<const uint4*>(sLo + n * 32);
    uint4* gh = reinterpret_cast<uint4*>(dH);
    uint4* gl = reinterpret_cast<uint4*>(dL);
#pragma unroll
    for (int i = 0; i < 4; i++) { gh[i] = sh[i]; gl[i] = sl[i]; }
}

// ======================= gate (register/shuffle, no smem x) =======================
// 4 threads per row: thread q accumulates over d = i*16 + q*4 + j.
__global__ void __launch_bounds__(256, 4)
gate_kernel(const float* __restrict__ x, const float* __restrict__ Wg,
            const float* __restrict__ bg)
{
    __shared__ int sH[LEAVES];
    const int tid = threadIdx.x;
    if (tid < LEAVES) sH[tid] = 0;
    __syncthreads();

    const int rloc = tid >> 2, q = tid & 3;
    const size_t row = (size_t)blockIdx.x * 64 + rloc;

    const float4* xv = reinterpret_cast<const float4*>(x + row * D);
    const float4* wv = reinterpret_cast<const float4*>(Wg);   // [D][4]

    float acc0 = 0.f, acc1 = 0.f, acc2 = 0.f, acc3 = 0.f;
#pragma unroll
    for (int i = 0; i < 16; i++) {
        float4 v = xv[i * 4 + q];               // lanes q=0..3 contiguous 64B
        int d0 = i * 16 + q * 4;
        float4 w0 = wv[d0], w1 = wv[d0 + 1], w2 = wv[d0 + 2], w3 = wv[d0 + 3];
        acc0 += v.x * w0.x + v.y * w1.x + v.z * w2.x + v.w * w3.x;
        acc1 += v.x * w0.y + v.y * w1.y + v.z * w2.y + v.w * w3.y;
        acc2 += v.x * w0.z + v.y * w1.z + v.z * w2.z + v.w * w3.z;
        acc3 += v.x * w0.w + v.y * w1.w + v.z * w2.w + v.w * w3.w;
    }
    // reduce across the 4 threads of this row
#pragma unroll
    for (int off = 1; off < 4; off <<= 1) {
        acc0 += __shfl_xor_sync(0xffffffffu, acc0, off);
        acc1 += __shfl_xor_sync(0xffffffffu, acc1, off);
        acc2 += __shfl_xor_sync(0xffffffffu, acc2, off);
        acc3 += __shfl_xor_sync(0xffffffffu, acc3, off);
    }
    if (q == 0) {
        float l0 = acc0 + bg[0], l1 = acc1 + bg[1];
        float l2 = acc2 + bg[2], l3 = acc3 + bg[3];
        float best = l0; int bi = 0;                 // first-max wins
        if (l1 > best) { best = l1; bi = 1; }
        if (l2 > best) { best = l2; bi = 2; }
        if (l3 > best) { best = l3; bi = 3; }
        g_idx[row] = bi;
        atomicAdd(&sH[bi], 1);
    }
    __syncthreads();
    if (tid < LEAVES) atomicAdd(&g_hist[tid], sH[tid]);
}

// counting-sort scatter: bases from local prefix of completed g_hist + cursor
__global__ void scatter_kernel() {
    __shared__ int cnt[LEAVES];
    __shared__ int boff[LEAVES];
    const int tid = threadIdx.x;
    const int r = blockIdx.x * blockDim.x + tid;
    if (tid < LEAVES) cnt[tid] = 0;
    __syncthreads();
    int e = g_idx[r];
    int my = atomicAdd(&cnt[e], 1);
    __syncthreads();
    if (tid < LEAVES) {
        int base = 0;
#pragma unroll
        for (int j = 0; j < LEAVES; j++)
            if (j < tid) base += g_hist[j];
        boff[tid] = base + atomicAdd(&g_cursor[tid], cnt[tid]);
    }
    __syncthreads();
    g_perm[boff[e] + my] = r;
}

// ======= main mma.sync kernel (R12 champion, byte-identical) =======
constexpr int A_STR_B   = 264 * 2;                 // 528
constexpr int OFF_AHI   = 0;                       // fp16(value) plane
constexpr int OFF_ABF   = 67584;                   // bf16(value) plane
constexpr int OFF_B     = 135168;
constexpr int B_PLANE_B = 256 * 40 * 2;            // 20480 (80B rows, k32)
constexpr int B_BUF_B   = 2 * B_PLANE_B;           // 40960
constexpr int OFF_BIAS  = OFF_B + 2 * B_BUF_B;     // 217088
constexpr int OFF_ORIG  = OFF_BIAS + 768 * 4;      // 220160
constexpr int MMA_SMEM  = OFF_ORIG + 512;          // 220672

__global__ void __launch_bounds__(512, 1)
tree_mma_kernel(const float* __restrict__ x,
                const float* __restrict__ b_leaf,
                const float* __restrict__ b_mid,
                const float* __restrict__ b_root,
                float* __restrict__ out)
{
    extern __shared__ char smc[];
    int* sOrig = reinterpret_cast<int*>(smc + OFF_ORIG);
    float* sBias = reinterpret_cast<float*>(smc + OFF_BIAS);
    const uint32_t sbU = smem_u32(smc);

    const int tid = threadIdx.x;
    const int lane = tid & 31, w = tid >> 5;       // 16 warps
    const int wm = w & 3, wn = w >> 2;             // 4 x 4 warp grid
    const int g = lane >> 2, tg = lane & 3;
    const size_t row0 = (size_t)blockIdx.x * 128;

    if (tid < 128) sOrig[tid] = g_perm[row0 + tid];
    __syncthreads();
    const int eL = g_idx[sOrig[0]];
    if (eL != g_idx[sOrig[127]]) return;          // mixed tile -> fallback
    const int eM = eL >> 1;
    const int matIdx[3] = { eL, 4 + eM, 6 };

    for (int i = tid; i < 256; i += 512) {
        sBias[i]       = b_leaf[eL * 256 + i];
        sBias[256 + i] = b_mid[eM * 256 + i];
        sBias[512 + i] = b_root[i];
    }

    // ---- A init: thread -> (row tid>>2, 64-col segment tid&3) ----
    {
        int r = tid >> 2, seg = tid & 3;
        const float4* xr = reinterpret_cast<const float4*>(
                               x + (size_t)sOrig[r] * D) + seg * 16;
        char* aH = smc + OFF_AHI + r * A_STR_B + seg * 128;
        char* aB = smc + OFF_ABF + r * A_STR_B + seg * 128;
#pragma unroll
        for (int i = 0; i < 16; i++) {
            float4 f = xr[i];
            uint2 hv, lv;
            hv.x = pack_h2(__float2half_rn(f.x), __float2half_rn(f.y));
            hv.y = pack_h2(__float2half_rn(f.z), __float2half_rn(f.w));
            lv.x = pack_bf2(__float2bfloat16(f.x), __float2bfloat16(f.y));
            lv.y = pack_bf2(__float2bfloat16(f.z), __float2bfloat16(f.w));
            *reinterpret_cast<uint2*>(aH + i * 8) = hv;
            *reinterpret_cast<uint2*>(aB + i * 8) = lv;
        }
    }

    // B staging coords: thread -> (plane sp, n-row sn); src 64B CONTIGUOUS
    const int sp = tid >> 8, sn = tid & 255;
    const uint32_t stgDstOff = sp * B_PLANE_B + sn * 80;

    // ---- stage B chunk 0 of layer 0 into buffer 0 (coalesced) ----
    {
        const uint4* src = reinterpret_cast<const uint4*>(
            g_wimg + (size_t)matIdx[0] * 131072 + sp * 8192 + sn * 32);
        uint4* dst = reinterpret_cast<uint4*>(smc + OFF_B + stgDstOff);
        dst[0] = src[0]; dst[1] = src[1]; dst[2] = src[2]; dst[3] = src[3];
    }
    __syncthreads();

    uint32_t aBase[2];
#pragma unroll
    for (int mt = 0; mt < 2; mt++)
        aBase[mt] = sbU + OFF_AHI
                  + (wm * 32 + mt * 16 + (lane & 15)) * A_STR_B
                  + (lane >> 4) * 16;
    const uint32_t bBase = sbU + OFF_B
        + (wn * 64 + (lane & 7) + ((lane >> 4) << 3)) * 80
        + (((lane >> 3) & 1) << 4);

    float acc[2][8][4];
#pragma unroll
    for (int mt = 0; mt < 2; mt++)
#pragma unroll
        for (int nt = 0; nt < 8; nt++)
#pragma unroll
            for (int q = 0; q < 4; q++) acc[mt][nt][q] = 0.f;

    int cur = 0;

#pragma unroll 1
    for (int l = 0; l < 3; l++) {
#pragma unroll 1
        for (int kc = 0; kc < 8; kc++) {
            bool hasNext = (kc < 7) || (l < 2);
            uint4 pf0, pf1, pf2, pf3;
            if (hasNext) {
                int nl  = (kc < 7) ? l : l + 1;
                int nkc = (kc < 7) ? kc + 1 : 0;
                const uint4* src = reinterpret_cast<const uint4*>(
                    g_wimg + (size_t)matIdx[nl] * 131072 + nkc * 16384
                    + sp * 8192 + sn * 32);
                pf0 = src[0]; pf1 = src[1]; pf2 = src[2]; pf3 = src[3];
            }

#pragma unroll
            for (int kk = 0; kk < 2; kk++) {
                const uint32_t koffA = kc * 64 + kk * 32;
                uint32_t aH[2][4], aB[2][4];
#pragma unroll
                for (int mt = 0; mt < 2; mt++) {
                    LDSM_X4(aH[mt][0], aH[mt][1], aH[mt][2], aH[mt][3],
                            aBase[mt] + koffA);
                    LDSM_X4(aB[mt][0], aB[mt][1], aB[mt][2], aB[mt][3],
                            aBase[mt] + (OFF_ABF - OFF_AHI) + koffA);
                }
                const uint32_t bk = bBase + cur * B_BUF_B + kk * 32;
#pragma unroll
                for (int op = 0; op < 4; op++) {
                    uint32_t bh0, bh1, bh2, bh3, bl0, bl1, bl2, bl3;
                    LDSM_X4(bh0, bh1, bh2, bh3, bk + op * (16 * 80));
                    LDSM_X4(bl0, bl1, bl2, bl3, bk + op * (16 * 80) + B_PLANE_B);
#pragma unroll
                    for (int mt = 0; mt < 2; mt++) {
                        mma_f16 (acc[mt][2 * op],     aH[mt], bh0, bh1);
                        mma_bf16(acc[mt][2 * op],     aB[mt], bl0, bl1);
                        mma_f16 (acc[mt][2 * op + 1], aH[mt], bh2, bh3);
                        mma_bf16(acc[mt][2 * op + 1], aB[mt], bl2, bl3);
                    }
                }
            }

            if (hasNext) {
                uint4* dst = reinterpret_cast<uint4*>(
                    smc + OFF_B + (cur ^ 1) * B_BUF_B + stgDstOff);
                dst[0] = pf0; dst[1] = pf1; dst[2] = pf2; dst[3] = pf3;
            }
            __syncthreads();
            cur ^= 1;
        }

        // ---- epilogue ----
        const float* sB = sBias + l * 256;
        if (l < 2) {
#pragma unroll
            for (int mt = 0; mt < 2; mt++) {
#pragma unroll
                for (int nt = 0; nt < 8; nt++) {
                    int col = wn * 64 + nt * 8 + tg * 2;
                    float b0 = sB[col], b1 = sB[col + 1];
                    int rlo = wm * 32 + mt * 16 + g;
#pragma unroll
                    for (int half = 0; half < 2; half++) {
                        int r = rlo + half * 8;
                        float v0 = fmaxf(acc[mt][nt][2 * half]     + b0, 0.f);
                        float v1 = fmaxf(acc[mt][nt][2 * half + 1] + b1, 0.f);
                        uint32_t hv = pack_h2(__float2half_rn(v0),
                                              __float2half_rn(v1));
                        uint32_t lv = pack_bf2(__float2bfloat16(v0),
                                               __float2bfloat16(v1));
                        char* pa = smc + OFF_AHI + r * A_STR_B + col * 2;
                        *reinterpret_cast<uint32_t*>(pa) = hv;
                        *reinterpret_cast<uint32_t*>(pa + (OFF_ABF - OFF_AHI)) = lv;
                        acc[mt][nt][2 * half] = 0.f;
                        acc[mt][nt][2 * half + 1] = 0.f;
                    }
                }
            }
            __syncthreads();
        } else {
#pragma unroll
            for (int mt = 0; mt < 2; mt++) {
#pragma unroll
                for (int half = 0; half < 2; half++) {
                    int r = wm * 32 + mt * 16 + g + half * 8;
                    float* orow = out + (size_t)sOrig[r] * D;
#pragma unroll
                    for (int nt = 0; nt < 8; nt++) {
                        int col = wn * 64 + nt * 8 + tg * 2;
                        float2 v;
                        v.x = fmaxf(acc[mt][nt][2 * half]     + sB[col],     0.f);
                        v.y = fmaxf(acc[mt][nt][2 * half + 1] + sB[col + 1], 0.f);
                        *reinterpret_cast<float2*>(orow + col) = v;
                    }
                }
            }
        }
    }
}

// ======================= FFMA2 fallback for mixed 128-tiles =======================
constexpr int FTILE = 64;
constexpr int FKC = 16;
constexpr int FSTR = D + 8;
constexpr int FOFF_SX = 0;
constexpr int FOFF_SW = FOFF_SX + FTILE * FSTR;
constexpr int FOFF_BLEAF = FOFF_SW + FKC * D;
constexpr int FOFF_BMID = FOFF_BLEAF + LEAVES * D;
constexpr int FOFF_BROOT = FOFF_BMID + MID * D;
constexpr int FOFF_ORIG = FOFF_BROOT + D;
constexpr int FOFF_E = FOFF_ORIG + FTILE;
constexpr int FOFF_MM = FOFF_E + FTILE;
constexpr int FB_BYTES = (FOFF_MM + 2) * (int)sizeof(float);

#define FMA_F32X2(d, a, b, c) \
    asm("fma.rn.f32x2 %0, %1, %2, %3;" : "=l"(d) : "l"(a), "l"(b), "l"(c))
#define PACK2(d, xx) \
    asm("mov.b64 %0, {%1, %1};" : "=l"(d) : "r"(xx))

template <bool MASKED>
__device__ __forceinline__
void fb_gemm(const float* __restrict__ Wglob, float* sW, const float* sX,
             const float m[8], u64 (&acc2)[8][4], int tid, int r0, int c0)
{
#pragma unroll 1
    for (int kc = 0; kc < D; kc += FKC) {
        __syncthreads();
        const float4* wg4 = reinterpret_cast<const float4*>(Wglob + (size_t)kc * D);
        float4* sW4 = reinterpret_cast<float4*>(sW);
#pragma unroll
        for (int i = 0; i < (FKC * D / 4) / 256; i++)
            sW4[tid + i * 256] = wg4[tid + i * 256];
        __syncthreads();
#pragma unroll
        for (int k4 = 0; k4 < FKC; k4 += 4) {
            float4 a4[8];
#pragma unroll
            for (int i = 0; i < 8; i++) {
                a4[i] = *reinterpret_cast<const float4*>(&sX[(r0 + i) * FSTR + kc + k4]);
                if (MASKED) {
                    a4[i].x *= m[i]; a4[i].y *= m[i];
                    a4[i].z *= m[i]; a4[i].w *= m[i];
                }
            }
#pragma unroll
            for (int kk = 0; kk < 4; kk++) {
                const ulonglong2* bp =
                    reinterpret_cast<const ulonglong2*>(&sW[(k4 + kk) * D + c0]);
                ulonglong2 b01 = bp[0];
                ulonglong2 b23 = bp[1];
#pragma unroll
                for (int i = 0; i < 8; i++) {
                    float av = (kk == 0) ? a4[i].x : (kk == 1) ? a4[i].y
                             : (kk == 2) ? a4[i].z : a4[i].w;
                    u64 a2;
                    PACK2(a2, __float_as_uint(av));
                    FMA_F32X2(acc2[i][0], a2, b01.x, acc2[i][0]);
                    FMA_F32X2(acc2[i][1], a2, b01.y, acc2[i][1]);
                    FMA_F32X2(acc2[i][2], a2, b23.x, acc2[i][2]);
                    FMA_F32X2(acc2[i][3], a2, b23.y, acc2[i][3]);
                }
            }
        }
    }
}

__global__ void __launch_bounds__(256, 2)
fallback_kernel(const float* __restrict__ x,
                const float* __restrict__ W_leaf, const float* __restrict__ b_leaf,
                const float* __restrict__ W_mid,  const float* __restrict__ b_mid,
                const float* __restrict__ W_root, const float* __restrict__ b_root,
                float* __restrict__ out)
{
    const size_t t128 = (size_t)(blockIdx.x >> 1) * 128;
    if (g_idx[g_perm[t128]] == g_idx[g_perm[t128 + 127]]) return;

    extern __shared__ float sm[];
    float* sX = sm + FOFF_SX;  float* sW = sm + FOFF_SW;
    float* sBlf = sm + FOFF_BLEAF;  float* sBmd = sm + FOFF_BMID;
    float* sBrt = sm + FOFF_BROOT;
    int* sOrig = reinterpret_cast<int*>(sm + FOFF_ORIG);
    int* sE = reinterpret_cast<int*>(sm + FOFF_E);
    int* sMM = reinterpret_cast<int*>(sm + FOFF_MM);

    const int tid = threadIdx.x;
    const size_t row0 = (size_t)blockIdx.x * FTILE;
    const int tx = tid & 31, ty = tid >> 5;
    const int r0 = ty * 8, c0 = tx * 8;

    if (tid < FTILE) {
        int orig = g_perm[row0 + tid];
        sOrig[tid] = orig;
        sE[tid] = g_idx[orig];
    }
    if (tid == FTILE) { sMM[0] = LEAVES; sMM[1] = -1; }
    __syncthreads();

#pragma unroll
    for (int i = 0; i < (FTILE * D / 4) / 256; i++) {
        int li = tid + i * 256;
        int r = li / (D / 4), c4 = li % (D / 4);
        const float4* src = reinterpret_cast<const float4*>(x + (size_t)sOrig[r] * D);
        float4 v = src[c4];
        float* dst = &sX[r * FSTR + c4 * 4];
        dst[0] = v.x; dst[1] = v.y; dst[2] = v.z; dst[3] = v.w;
    }
    for (int i = tid; i < LEAVES * D; i += 256) sBlf[i] = b_leaf[i];
    for (int i = tid; i < MID * D;    i += 256) sBmd[i] = b_mid[i];
    for (int i = tid; i < D;          i += 256) sBrt[i] = b_root[i];
    if (tid < FTILE) {
        atomicMin(&sMM[0], sE[tid]);
        atomicMax(&sMM[1], sE[tid]);
    }
    __syncthreads();

    const int emin = sMM[0], emax = sMM[1];
    u64 acc2[8][4];
#pragma unroll
    for (int i = 0; i < 8; i++)
#pragma unroll
        for (int j = 0; j < 4; j++) acc2[i][j] = 0ull;
    float m[8];

    if (emin == emax) {
        fb_gemm<false>(W_leaf + (size_t)emin * D * D, sW, sX, m, acc2, tid, r0, c0);
    } else {
        for (int e = emin; e <= emax; e++) {
#pragma unroll
            for (int i = 0; i < 8; i++) m[i] = (sE[r0 + i] == e) ? 1.f : 0.f;
            fb_gemm<true>(W_leaf + (size_t)e * D * D, sW, sX, m, acc2, tid, r0, c0);
        }
    }
#pragma unroll
    for (int i = 0; i < 8; i++) {
        int e = sE[r0 + i];
#pragma unroll
        for (int p = 0; p < 4; p++) {
            U64F2 u; u.u = acc2[i][p];
            sX[(r0 + i) * FSTR + c0 + 2 * p]     = fmaxf(u.f.x + sBlf[e * D + c0 + 2 * p], 0.f);
            sX[(r0 + i) * FSTR + c0 + 2 * p + 1] = fmaxf(u.f.y + sBlf[e * D + c0 + 2 * p + 1], 0.f);
            acc2[i][p] = 0ull;
        }
    }

    const int pmin = emin >> 1, pmax = emax >> 1;
    if (pmin == pmax) {
        fb_gemm<false>(W_mid + (size_t)pmin * D * D, sW, sX, m, acc2, tid, r0, c0);
    } else {
        for (int p = pmin; p <= pmax; p++) {
#pragma unroll
            for (int i = 0; i < 8; i++) m[i] = ((sE[r0 + i] >> 1) == p) ? 1.f : 0.f;
            fb_gemm<true>(W_mid + (size_t)p * D * D, sW, sX, m, acc2, tid, r0, c0);
        }
    }
#pragma unroll
    for (int i = 0; i < 8; i++) {
        int pp = sE[r0 + i] >> 1;
#pragma unroll
        for (int p = 0; p < 4; p++) {
            U64F2 u; u.u = acc2[i][p];
            sX[(r0 + i) * FSTR + c0 + 2 * p]     = fmaxf(u.f.x + sBmd[pp * D + c0 + 2 * p], 0.f);
            sX[(r0 + i) * FSTR + c0 + 2 * p + 1] = fmaxf(u.f.y + sBmd[pp * D + c0 + 2 * p + 1], 0.f);
            acc2[i][p] = 0ull;
        }
    }

    fb_gemm<false>(W_root, sW, sX, m, acc2, tid, r0, c0);
#pragma unroll
    for (int i = 0; i < 8; i++) {
        float v[8];
#pragma unroll
        for (int p = 0; p < 4; p++) {
            U64F2 u; u.u = acc2[i][p];
            v[2 * p]     = fmaxf(u.f.x + sBrt[c0 + 2 * p],     0.f);
            v[2 * p + 1] = fmaxf(u.f.y + sBrt[c0 + 2 * p + 1], 0.f);
        }
        float4* o = reinterpret_cast<float4*>(out + (size_t)sOrig[r0 + i] * D + c0);
        o[0] = make_float4(v[0], v[1], v[2], v[3]);
        o[1] = make_float4(v[4], v[5], v[6], v[7]);
    }
}

// ======================= launch =======================
extern "C" void kernel_launch(void* const* d_in, const int* in_sizes, int n_in,
                              void* d_out, int out_size)
{
    const float* x      = (const float*)d_in[0];
    const float* Wg     = (const float*)d_in[1];
    const float* bg     = (const float*)d_in[2];
    const float* W_leaf = (const float*)d_in[3];
    const float* b_leaf = (const float*)d_in[4];
    const float* W_mid  = (const float*)d_in[5];
    const float* b_mid  = (const float*)d_in[6];
    const float* W_root = (const float*)d_in[7];
    const float* b_root = (const float*)d_in[8];
    float* out = (float*)d_out;

    cudaFuncSetAttribute(tree_mma_kernel,
                         cudaFuncAttributeMaxDynamicSharedMemorySize, MMA_SMEM);
    cudaFuncSetAttribute(fallback_kernel,
                         cudaFuncAttributeMaxDynamicSharedMemorySize, FB_BYTES);

    prep_w_kernel<<<7 * 8, 256>>>(W_leaf, W_mid, W_root);
    gate_kernel<<<NB / 64, 256>>>(x, Wg, bg);
    scatter_kernel<<<NB / 256, 256>>>();
    tree_mma_kernel<<<NB / 128, 512, MMA_SMEM>>>(x, b_leaf, b_mid, b_root, out);
    fallback_kernel<<<NB / FTILE, 256, FB_BYTES>>>(
        x, W_leaf, b_leaf, W_mid, b_mid, W_root, b_root, out);
}